// round 16
// baseline (speedup 1.0000x reference)
#include <cuda_runtime.h>
#include <cstdint>

#define N_POI_C  100000
#define N_EDGE_C 50000
#define NNZ_MAX  3200000
#define EMB      128
#define SCAN_B   1024

// ---------------- scratch: TWO independent CSR buffer sets (for stream overlap) ----
__device__ int   g_cnt0[N_EDGE_C];
__device__ int   g_rowptr0[N_EDGE_C + 1];
__device__ int   g_cursor0[N_EDGE_C];
__device__ int   g_bsum0[128];
__device__ int2  g_pack0[NNZ_MAX];

__device__ int   g_cnt1[N_POI_C];
__device__ int   g_rowptr1[N_POI_C + 1];
__device__ int   g_cursor1[N_POI_C];
__device__ int   g_bsum1[128];
__device__ int2  g_pack1[NNZ_MAX];

__device__ float g_E2[(size_t)N_EDGE_C * EMB];          // edge @ Wc2
__device__ float g_Wc1[EMB * EMB];                      // W_poi  @ Wf[0:128]
__device__ float g_Wc2[EMB * EMB];                      // W_edge @ Wf[128:256]

template<int S> __device__ __forceinline__ int*  CNT()    { return S ? g_cnt1    : g_cnt0; }
template<int S> __device__ __forceinline__ int*  ROWPTR() { return S ? g_rowptr1 : g_rowptr0; }
template<int S> __device__ __forceinline__ int*  CURSOR() { return S ? g_cursor1 : g_cursor0; }
template<int S> __device__ __forceinline__ int*  BSUM()   { return S ? g_bsum1   : g_bsum0; }
template<int S> __device__ __forceinline__ int2* PACK()   { return S ? g_pack1   : g_pack0; }

// ---------------- tiny weight-fold GEMMs: Wc1/Wc2 (128x128 each) ----------------
__global__ void wc_kernel(const float* __restrict__ Wp,
                          const float* __restrict__ We,
                          const float* __restrict__ Wf) {
    __shared__ float srow[EMB];
    int i = blockIdx.x;
    int j = threadIdx.x;
    const float* W  = blockIdx.y ? We : Wp;
    const float* Bf = Wf + (blockIdx.y ? EMB * EMB : 0);
    srow[j] = W[i * EMB + j];
    __syncthreads();
    float acc = 0.f;
#pragma unroll 8
    for (int k = 0; k < EMB; ++k)
        acc = fmaf(srow[k], Bf[k * EMB + j], acc);
    (blockIdx.y ? g_Wc2 : g_Wc1)[i * EMB + j] = acc;
}

// ---------------- CSR build ----------------
template<int S>
__global__ void zero_kernel(int n) {
    int* cnt = CNT<S>();
    for (int i = blockIdx.x * blockDim.x + threadIdx.x; i < n;
         i += gridDim.x * blockDim.x)
        cnt[i] = 0;
}

template<int S>
__global__ void hist_kernel(const int* __restrict__ rows, int nnz) {
    int* cnt = CNT<S>();
    int stride = gridDim.x * blockDim.x;
    int tid = blockIdx.x * blockDim.x + threadIdx.x;
    int n4 = nnz >> 2;
    const int4* r4 = (const int4*)rows;
    for (int i = tid; i < n4; i += stride) {
        int4 r = __ldg(r4 + i);
        atomicAdd(&cnt[r.x], 1);
        atomicAdd(&cnt[r.y], 1);
        atomicAdd(&cnt[r.z], 1);
        atomicAdd(&cnt[r.w], 1);
    }
    for (int i = n4 * 4 + tid; i < nnz; i += stride)
        atomicAdd(&cnt[rows[i]], 1);
}

template<int S>
__global__ __launch_bounds__(SCAN_B) void scan_pass1(int n) {
    __shared__ int ws[32];
    int tid = threadIdx.x, lane = tid & 31, wid = tid >> 5;
    int i = blockIdx.x * SCAN_B + tid;
    int s = (i < n) ? CNT<S>()[i] : 0;
#pragma unroll
    for (int d = 16; d > 0; d >>= 1) s += __shfl_down_sync(0xFFFFFFFFu, s, d);
    if (lane == 0) ws[wid] = s;
    __syncthreads();
    if (wid == 0) {
        int t = ws[lane];
#pragma unroll
        for (int d = 16; d > 0; d >>= 1) t += __shfl_down_sync(0xFFFFFFFFu, t, d);
        if (lane == 0) BSUM<S>()[blockIdx.x] = t;
    }
}

template<int S>
__global__ __launch_bounds__(SCAN_B) void scan_pass3(int n) {
    __shared__ int ws[32];
    __shared__ int s_boff;
    int tid = threadIdx.x, lane = tid & 31, wid = tid >> 5;
    if (wid == 0) {
        int acc = 0;
        for (int b = lane; b < (int)blockIdx.x; b += 32) acc += BSUM<S>()[b];
#pragma unroll
        for (int d = 16; d > 0; d >>= 1) acc += __shfl_down_sync(0xFFFFFFFFu, acc, d);
        if (lane == 0) s_boff = acc;
    }
    int i = blockIdx.x * SCAN_B + tid;
    int v = (i < n) ? CNT<S>()[i] : 0;
    int x = v;
#pragma unroll
    for (int d = 1; d < 32; d <<= 1) {
        int t = __shfl_up_sync(0xFFFFFFFFu, x, d);
        if (lane >= d) x += t;
    }
    if (lane == 31) ws[wid] = x;
    __syncthreads();
    if (wid == 0) {
        int w = ws[lane];
#pragma unroll
        for (int d = 1; d < 32; d <<= 1) {
            int t = __shfl_up_sync(0xFFFFFFFFu, w, d);
            if (lane >= d) w += t;
        }
        ws[lane] = w;
    }
    __syncthreads();
    int woff = wid ? ws[wid - 1] : 0;
    int excl = (x - v) + woff + s_boff;
    if (i < n) {
        ROWPTR<S>()[i] = excl;
        CURSOR<S>()[i] = excl;
        if (i == n - 1) ROWPTR<S>()[n] = excl + v;
    }
}

template<int S>
__global__ void scatter_kernel(const int* __restrict__ rows,
                               const int* __restrict__ cols,
                               const float* __restrict__ vals, int nnz) {
    int*  cur  = CURSOR<S>();
    int2* pack = PACK<S>();
    int stride = gridDim.x * blockDim.x;
    int tid = blockIdx.x * blockDim.x + threadIdx.x;
    int n4 = nnz >> 2;
    const int4*   r4 = (const int4*)rows;
    const int4*   c4 = (const int4*)cols;
    const float4* v4 = (const float4*)vals;
    for (int i = tid; i < n4; i += stride) {
        int4 r = __ldg(r4 + i);
        int4 c = __ldg(c4 + i);
        float4 v = __ldg(v4 + i);
        int p0 = atomicAdd(&cur[r.x], 1);
        int p1 = atomicAdd(&cur[r.y], 1);
        int p2 = atomicAdd(&cur[r.z], 1);
        int p3 = atomicAdd(&cur[r.w], 1);
        pack[p0] = make_int2(c.x, __float_as_int(v.x));
        pack[p1] = make_int2(c.y, __float_as_int(v.y));
        pack[p2] = make_int2(c.z, __float_as_int(v.z));
        pack[p3] = make_int2(c.w, __float_as_int(v.w));
    }
    for (int i = n4 * 4 + tid; i < nnz; i += stride) {
        int pos = atomicAdd(&cur[rows[i]], 1);
        pack[pos] = make_int2(cols[i], __float_as_int(vals[i]));
    }
}

// ---- SpMM1 fused: S1row = pte-row gather; F[r] = S1row @ Wc1 + E2[r] ------------
// One warp per output row; lane holds S1 cols [4*lane, 4*lane+4).
__global__ __launch_bounds__(128) void spmm1_fused_kernel(const float* __restrict__ dense,
                                                          float* __restrict__ F,
                                                          int nrows) {
    int r = blockIdx.x * 4 + (threadIdx.x >> 5);
    if (r >= nrows) return;
    int lane = threadIdx.x & 31;
    const int*  rowptr = ROWPTR<0>();
    const int2* pack   = PACK<0>();
    int s = __ldg(&rowptr[r]);
    int e = __ldg(&rowptr[r + 1]);
    float4 acc = make_float4(0.f, 0.f, 0.f, 0.f);
    int j = s;
    for (; j + 4 <= e; j += 4) {
        int2 p0 = __ldg(&pack[j + 0]);
        int2 p1 = __ldg(&pack[j + 1]);
        int2 p2 = __ldg(&pack[j + 2]);
        int2 p3 = __ldg(&pack[j + 3]);
        float4 d0 = __ldg((const float4*)(dense + (size_t)p0.x * EMB) + lane);
        float4 d1 = __ldg((const float4*)(dense + (size_t)p1.x * EMB) + lane);
        float4 d2 = __ldg((const float4*)(dense + (size_t)p2.x * EMB) + lane);
        float4 d3 = __ldg((const float4*)(dense + (size_t)p3.x * EMB) + lane);
        float v0 = __int_as_float(p0.y), v1 = __int_as_float(p1.y);
        float v2 = __int_as_float(p2.y), v3 = __int_as_float(p3.y);
        acc.x = fmaf(v0, d0.x, acc.x); acc.y = fmaf(v0, d0.y, acc.y);
        acc.z = fmaf(v0, d0.z, acc.z); acc.w = fmaf(v0, d0.w, acc.w);
        acc.x = fmaf(v1, d1.x, acc.x); acc.y = fmaf(v1, d1.y, acc.y);
        acc.z = fmaf(v1, d1.z, acc.z); acc.w = fmaf(v1, d1.w, acc.w);
        acc.x = fmaf(v2, d2.x, acc.x); acc.y = fmaf(v2, d2.y, acc.y);
        acc.z = fmaf(v2, d2.z, acc.z); acc.w = fmaf(v2, d2.w, acc.w);
        acc.x = fmaf(v3, d3.x, acc.x); acc.y = fmaf(v3, d3.y, acc.y);
        acc.z = fmaf(v3, d3.z, acc.z); acc.w = fmaf(v3, d3.w, acc.w);
    }
    for (; j < e; ++j) {
        int2 p = __ldg(&pack[j]);
        float4 d = __ldg((const float4*)(dense + (size_t)p.x * EMB) + lane);
        float v = __int_as_float(p.y);
        acc.x = fmaf(v, d.x, acc.x); acc.y = fmaf(v, d.y, acc.y);
        acc.z = fmaf(v, d.z, acc.z); acc.w = fmaf(v, d.w, acc.w);
    }

    // ---- fused epilogue: f = acc_row @ Wc1 + E2[r] (per-warp GEMV) ----
    float4 f = __ldg((const float4*)(g_E2 + (size_t)r * EMB) + lane);
    const float* wbase = (const float*)g_Wc1 + lane * 4;   // this lane's 4 cols
#pragma unroll 4
    for (int k4 = 0; k4 < 32; ++k4) {
        float sx = __shfl_sync(0xFFFFFFFFu, acc.x, k4);
        float sy = __shfl_sync(0xFFFFFFFFu, acc.y, k4);
        float sz = __shfl_sync(0xFFFFFFFFu, acc.z, k4);
        float sw = __shfl_sync(0xFFFFFFFFu, acc.w, k4);
        const float* w = wbase + (size_t)(k4 * 4) * EMB;
        float4 w0 = __ldg((const float4*)(w));
        float4 w1 = __ldg((const float4*)(w + EMB));
        float4 w2 = __ldg((const float4*)(w + 2 * EMB));
        float4 w3 = __ldg((const float4*)(w + 3 * EMB));
        f.x = fmaf(sx, w0.x, f.x); f.y = fmaf(sx, w0.y, f.y);
        f.z = fmaf(sx, w0.z, f.z); f.w = fmaf(sx, w0.w, f.w);
        f.x = fmaf(sy, w1.x, f.x); f.y = fmaf(sy, w1.y, f.y);
        f.z = fmaf(sy, w1.z, f.z); f.w = fmaf(sy, w1.w, f.w);
        f.x = fmaf(sz, w2.x, f.x); f.y = fmaf(sz, w2.y, f.y);
        f.z = fmaf(sz, w2.z, f.z); f.w = fmaf(sz, w2.w, f.w);
        f.x = fmaf(sw, w3.x, f.x); f.y = fmaf(sw, w3.y, f.y);
        f.z = fmaf(sw, w3.z, f.z); f.w = fmaf(sw, w3.w, f.w);
    }
    *(float4*)(F + (size_t)r * EMB + lane * 4) = f;
}

// ---------------- SpMM2: plain CSR SpMM (set 1), one warp per row ----------------
__global__ __launch_bounds__(128) void spmm2_kernel(const float* __restrict__ dense,
                                                    float* __restrict__ out,
                                                    int nrows) {
    int r = blockIdx.x * 4 + (threadIdx.x >> 5);
    if (r >= nrows) return;
    int lane = threadIdx.x & 31;
    const int*  rowptr = ROWPTR<1>();
    const int2* pack   = PACK<1>();
    int s = __ldg(&rowptr[r]);
    int e = __ldg(&rowptr[r + 1]);
    float4 acc = make_float4(0.f, 0.f, 0.f, 0.f);
    int j = s;
    for (; j + 4 <= e; j += 4) {
        int2 p0 = __ldg(&pack[j + 0]);
        int2 p1 = __ldg(&pack[j + 1]);
        int2 p2 = __ldg(&pack[j + 2]);
        int2 p3 = __ldg(&pack[j + 3]);
        float4 d0 = __ldg((const float4*)(dense + (size_t)p0.x * EMB) + lane);
        float4 d1 = __ldg((const float4*)(dense + (size_t)p1.x * EMB) + lane);
        float4 d2 = __ldg((const float4*)(dense + (size_t)p2.x * EMB) + lane);
        float4 d3 = __ldg((const float4*)(dense + (size_t)p3.x * EMB) + lane);
        float v0 = __int_as_float(p0.y), v1 = __int_as_float(p1.y);
        float v2 = __int_as_float(p2.y), v3 = __int_as_float(p3.y);
        acc.x = fmaf(v0, d0.x, acc.x); acc.y = fmaf(v0, d0.y, acc.y);
        acc.z = fmaf(v0, d0.z, acc.z); acc.w = fmaf(v0, d0.w, acc.w);
        acc.x = fmaf(v1, d1.x, acc.x); acc.y = fmaf(v1, d1.y, acc.y);
        acc.z = fmaf(v1, d1.z, acc.z); acc.w = fmaf(v1, d1.w, acc.w);
        acc.x = fmaf(v2, d2.x, acc.x); acc.y = fmaf(v2, d2.y, acc.y);
        acc.z = fmaf(v2, d2.z, acc.z); acc.w = fmaf(v2, d2.w, acc.w);
        acc.x = fmaf(v3, d3.x, acc.x); acc.y = fmaf(v3, d3.y, acc.y);
        acc.z = fmaf(v3, d3.z, acc.z); acc.w = fmaf(v3, d3.w, acc.w);
    }
    for (; j < e; ++j) {
        int2 p = __ldg(&pack[j]);
        float4 d = __ldg((const float4*)(dense + (size_t)p.x * EMB) + lane);
        float v = __int_as_float(p.y);
        acc.x = fmaf(v, d.x, acc.x); acc.y = fmaf(v, d.y, acc.y);
        acc.z = fmaf(v, d.z, acc.z); acc.w = fmaf(v, d.w, acc.w);
    }
    *(float4*)(out + (size_t)r * EMB + lane * 4) = acc;
}

// ---------------- gemmB (tf32 tensor): E2 = edge @ Wc2 (overwrite) ----------------
// block tile 64(M) x 128(N), 8 warps as 4x2 grid of 16x64 warp tiles,
// K=128 staged through smem in 32-chunks as pre-converted tf32 bits.
__device__ __forceinline__ uint32_t f2tf(float x) {
    uint32_t r;
    asm("cvt.rna.tf32.f32 %0, %1;" : "=r"(r) : "f"(x));
    return r;
}

__global__ __launch_bounds__(256) void gemmB_tf32(const float* __restrict__ E,
                                                  int nrows) {
    __shared__ uint32_t sA[64][36];
    __shared__ uint32_t sB[32][132];
    int tid  = threadIdx.x;
    int warp = tid >> 5, lane = tid & 31;
    int g = lane >> 2, t = lane & 3;
    int m0 = (warp & 3) * 16;
    int n0 = (warp >> 2) * 64;
    int row0 = blockIdx.x * 64;
    const float* B = (const float*)g_Wc2;
    float* O = (float*)g_E2;

    float acc[8][4];
#pragma unroll
    for (int ng = 0; ng < 8; ++ng)
#pragma unroll
        for (int c = 0; c < 4; ++c) acc[ng][c] = 0.f;

#pragma unroll 1
    for (int chunk = 0; chunk < 4; ++chunk) {
        int k0 = chunk * 32;
#pragma unroll
        for (int q = 0; q < 2; ++q) {
            int lin = tid * 2 + q;
            int m = lin >> 3;
            int kk = (lin & 7) * 4;
            float4 a4 = (row0 + m < nrows)
                ? *(const float4*)(E + (size_t)(row0 + m) * EMB + k0 + kk)
                : make_float4(0.f, 0.f, 0.f, 0.f);
            sA[m][kk + 0] = f2tf(a4.x); sA[m][kk + 1] = f2tf(a4.y);
            sA[m][kk + 2] = f2tf(a4.z); sA[m][kk + 3] = f2tf(a4.w);
        }
#pragma unroll
        for (int q = 0; q < 4; ++q) {
            int lin = tid * 4 + q;
            int k = lin >> 5;
            int c4 = (lin & 31) * 4;
            float4 b4 = *(const float4*)(B + (size_t)(k0 + k) * EMB + c4);
            sB[k][c4 + 0] = f2tf(b4.x); sB[k][c4 + 1] = f2tf(b4.y);
            sB[k][c4 + 2] = f2tf(b4.z); sB[k][c4 + 3] = f2tf(b4.w);
        }
        __syncthreads();
#pragma unroll
        for (int ks = 0; ks < 32; ks += 8) {
            uint32_t a0 = sA[m0 + g][ks + t];
            uint32_t a1 = sA[m0 + g + 8][ks + t];
            uint32_t a2 = sA[m0 + g][ks + t + 4];
            uint32_t a3 = sA[m0 + g + 8][ks + t + 4];
#pragma unroll
            for (int ng = 0; ng < 8; ++ng) {
                uint32_t b0 = sB[ks + t][n0 + ng * 8 + g];
                uint32_t b1 = sB[ks + t + 4][n0 + ng * 8 + g];
                asm volatile(
                    "mma.sync.aligned.m16n8k8.row.col.f32.tf32.tf32.f32 "
                    "{%0,%1,%2,%3}, {%4,%5,%6,%7}, {%8,%9}, {%0,%1,%2,%3};\n"
                    : "+f"(acc[ng][0]), "+f"(acc[ng][1]),
                      "+f"(acc[ng][2]), "+f"(acc[ng][3])
                    : "r"(a0), "r"(a1), "r"(a2), "r"(a3), "r"(b0), "r"(b1));
            }
        }
        __syncthreads();
    }
    int r1 = row0 + m0 + g, r2 = r1 + 8;
#pragma unroll
    for (int ng = 0; ng < 8; ++ng) {
        int c0 = n0 + ng * 8 + t * 2;
        if (r1 < nrows)
            *(float2*)(O + (size_t)r1 * EMB + c0) = make_float2(acc[ng][0], acc[ng][1]);
        if (r2 < nrows)
            *(float2*)(O + (size_t)r2 * EMB + c0) = make_float2(acc[ng][2], acc[ng][3]);
    }
}

// ---------------- launch ----------------
template<int S>
static inline void build_csr(const int* rows, const int* cols, const float* vals,
                             int nnz, int nrows, cudaStream_t st) {
    int nblocks = (nrows + SCAN_B - 1) / SCAN_B;
    zero_kernel<S><<<256, 256, 0, st>>>(nrows);
    hist_kernel<S><<<1024, 256, 0, st>>>(rows, nnz);
    scan_pass1<S><<<nblocks, SCAN_B, 0, st>>>(nrows);
    scan_pass3<S><<<nblocks, SCAN_B, 0, st>>>(nrows);
    scatter_kernel<S><<<1024, 256, 0, st>>>(rows, cols, vals, nnz);
}

static cudaStream_t g_s2  = nullptr;   // CSR2 build
static cudaStream_t g_s3  = nullptr;   // wc + gemmB
static cudaEvent_t  g_evF = nullptr;   // fork
static cudaEvent_t  g_evJ = nullptr;   // CSR2 done
static cudaEvent_t  g_evB = nullptr;   // wc+gemmB done

extern "C" void kernel_launch(void* const* d_in, const int* in_sizes, int n_in,
                              void* d_out, int out_size) {
    const float* poi  = (const float*)d_in[0];
    const float* edge = (const float*)d_in[1];
    const int*   pr   = (const int*)d_in[2];
    const int*   pc   = (const int*)d_in[3];
    const float* pv   = (const float*)d_in[4];
    const int*   er   = (const int*)d_in[5];
    const int*   ec   = (const int*)d_in[6];
    const float* evv  = (const float*)d_in[7];
    const float* Wp   = (const float*)d_in[8];
    const float* We   = (const float*)d_in[9];
    const float* Wf   = (const float*)d_in[10];
    int nnz1 = in_sizes[2];
    int nnz2 = in_sizes[5];

    float* prop = (float*)d_out;                       // [100000, 128]
    float* F    = prop + (size_t)N_POI_C * EMB;        // [50000, 128]

    if (!g_s2) {
        cudaStreamCreateWithFlags(&g_s2, cudaStreamNonBlocking);
        cudaStreamCreateWithFlags(&g_s3, cudaStreamNonBlocking);
        cudaEventCreateWithFlags(&g_evF, cudaEventDisableTiming);
        cudaEventCreateWithFlags(&g_evJ, cudaEventDisableTiming);
        cudaEventCreateWithFlags(&g_evB, cudaEventDisableTiming);
    }

    // ---- fork ----
    cudaEventRecord(g_evF, 0);

    // side stream A: CSR build for etp (set 1)
    cudaStreamWaitEvent(g_s2, g_evF, 0);
    build_csr<1>(er, ec, evv, nnz2, N_POI_C, g_s2);
    cudaEventRecord(g_evJ, g_s2);

    // side stream B: weight fold, then E2 = edge @ Wc2 (tf32; hidden under CSR1)
    cudaStreamWaitEvent(g_s3, g_evF, 0);
    wc_kernel<<<dim3(128, 2), 128, 0, g_s3>>>(Wp, We, Wf);
    gemmB_tf32<<<(N_EDGE_C + 63) / 64, 256, 0, g_s3>>>(edge, N_EDGE_C);
    cudaEventRecord(g_evB, g_s3);

    // main (critical path): CSR for pte (set 0)
    build_csr<0>(pr, pc, pv, nnz1, N_EDGE_C, 0);

    // main: fused SpMM1 + per-row GEMV epilogue -> F  (needs Wc1 + E2 ready)
    cudaStreamWaitEvent(0, g_evB, 0);
    spmm1_fused_kernel<<<(N_EDGE_C + 3) / 4, 128>>>(poi, F, N_EDGE_C);

    // join CSR2, then SpMM2: prop = etp @ F
    cudaStreamWaitEvent(0, g_evJ, 0);
    spmm2_kernel<<<(N_POI_C + 3) / 4, 128>>>(F, prop, N_POI_C);
}

// round 17
// speedup vs baseline: 1.1497x; 1.1497x over previous
#include <cuda_runtime.h>
#include <cstdint>

#define N_POI_C  100000
#define N_EDGE_C 50000
#define NNZ_MAX  3200000
#define EMB      128
#define SCAN_B   1024

// ---------------- scratch: TWO independent CSR buffer sets (for stream overlap) ----
// NOTE: g_cnt* start zero (static init) and are re-zeroed by scan_pass3 each run,
// so no explicit zero kernel is needed and graph replays stay idempotent.
__device__ int   g_cnt0[N_EDGE_C];
__device__ int   g_rowptr0[N_EDGE_C + 1];
__device__ int   g_cursor0[N_EDGE_C];
__device__ int   g_bsum0[128];
__device__ int2  g_pack0[NNZ_MAX];

__device__ int   g_cnt1[N_POI_C];
__device__ int   g_rowptr1[N_POI_C + 1];
__device__ int   g_cursor1[N_POI_C];
__device__ int   g_bsum1[128];
__device__ int2  g_pack1[NNZ_MAX];

__device__ float g_S1[(size_t)N_EDGE_C * EMB];          // spmm(pte, poi_embs)
__device__ float g_Wc1[EMB * EMB];                      // W_poi  @ Wf[0:128]
__device__ float g_Wc2[EMB * EMB];                      // W_edge @ Wf[128:256]

template<int S> __device__ __forceinline__ int*  CNT()    { return S ? g_cnt1    : g_cnt0; }
template<int S> __device__ __forceinline__ int*  ROWPTR() { return S ? g_rowptr1 : g_rowptr0; }
template<int S> __device__ __forceinline__ int*  CURSOR() { return S ? g_cursor1 : g_cursor0; }
template<int S> __device__ __forceinline__ int*  BSUM()   { return S ? g_bsum1   : g_bsum0; }
template<int S> __device__ __forceinline__ int2* PACK()   { return S ? g_pack1   : g_pack0; }

// ---------------- tiny weight-fold GEMMs: Wc1/Wc2 (128x128 each) ----------------
__global__ void wc_kernel(const float* __restrict__ Wp,
                          const float* __restrict__ We,
                          const float* __restrict__ Wf) {
    __shared__ float srow[EMB];
    int i = blockIdx.x;
    int j = threadIdx.x;
    const float* W  = blockIdx.y ? We : Wp;
    const float* Bf = Wf + (blockIdx.y ? EMB * EMB : 0);
    srow[j] = W[i * EMB + j];
    __syncthreads();
    float acc = 0.f;
#pragma unroll 8
    for (int k = 0; k < EMB; ++k)
        acc = fmaf(srow[k], Bf[k * EMB + j], acc);
    (blockIdx.y ? g_Wc2 : g_Wc1)[i * EMB + j] = acc;
}

// ---------------- CSR build ----------------
template<int S>
__global__ void hist_kernel(const int* __restrict__ rows, int nnz) {
    int* cnt = CNT<S>();
    int stride = gridDim.x * blockDim.x;
    int tid = blockIdx.x * blockDim.x + threadIdx.x;
    int n4 = nnz >> 2;
    const int4* r4 = (const int4*)rows;
    for (int i = tid; i < n4; i += stride) {
        int4 r = __ldg(r4 + i);
        atomicAdd(&cnt[r.x], 1);
        atomicAdd(&cnt[r.y], 1);
        atomicAdd(&cnt[r.z], 1);
        atomicAdd(&cnt[r.w], 1);
    }
    for (int i = n4 * 4 + tid; i < nnz; i += stride)
        atomicAdd(&cnt[rows[i]], 1);
}

template<int S>
__global__ __launch_bounds__(SCAN_B) void scan_pass1(int n) {
    __shared__ int ws[32];
    int tid = threadIdx.x, lane = tid & 31, wid = tid >> 5;
    int i = blockIdx.x * SCAN_B + tid;
    int s = (i < n) ? CNT<S>()[i] : 0;
#pragma unroll
    for (int d = 16; d > 0; d >>= 1) s += __shfl_down_sync(0xFFFFFFFFu, s, d);
    if (lane == 0) ws[wid] = s;
    __syncthreads();
    if (wid == 0) {
        int t = ws[lane];
#pragma unroll
        for (int d = 16; d > 0; d >>= 1) t += __shfl_down_sync(0xFFFFFFFFu, t, d);
        if (lane == 0) BSUM<S>()[blockIdx.x] = t;
    }
}

// pass 3 (fused pass 2): per-block prefix over bsum, scan 1024 elems, write
// rowptr/cursor, and RE-ZERO cnt for the next replay (removes zero_kernel).
template<int S>
__global__ __launch_bounds__(SCAN_B) void scan_pass3(int n) {
    __shared__ int ws[32];
    __shared__ int s_boff;
    int tid = threadIdx.x, lane = tid & 31, wid = tid >> 5;
    if (wid == 0) {
        int acc = 0;
        for (int b = lane; b < (int)blockIdx.x; b += 32) acc += BSUM<S>()[b];
#pragma unroll
        for (int d = 16; d > 0; d >>= 1) acc += __shfl_down_sync(0xFFFFFFFFu, acc, d);
        if (lane == 0) s_boff = acc;
    }
    int i = blockIdx.x * SCAN_B + tid;
    int v = (i < n) ? CNT<S>()[i] : 0;
    int x = v;
#pragma unroll
    for (int d = 1; d < 32; d <<= 1) {
        int t = __shfl_up_sync(0xFFFFFFFFu, x, d);
        if (lane >= d) x += t;
    }
    if (lane == 31) ws[wid] = x;
    __syncthreads();
    if (wid == 0) {
        int w = ws[lane];
#pragma unroll
        for (int d = 1; d < 32; d <<= 1) {
            int t = __shfl_up_sync(0xFFFFFFFFu, w, d);
            if (lane >= d) w += t;
        }
        ws[lane] = w;
    }
    __syncthreads();
    int woff = wid ? ws[wid - 1] : 0;
    int excl = (x - v) + woff + s_boff;
    if (i < n) {
        ROWPTR<S>()[i] = excl;
        CURSOR<S>()[i] = excl;
        CNT<S>()[i] = 0;                 // re-zero for next run
        if (i == n - 1) ROWPTR<S>()[n] = excl + v;
    }
}

template<int S>
__global__ void scatter_kernel(const int* __restrict__ rows,
                               const int* __restrict__ cols,
                               const float* __restrict__ vals, int nnz) {
    int*  cur  = CURSOR<S>();
    int2* pack = PACK<S>();
    int stride = gridDim.x * blockDim.x;
    int tid = blockIdx.x * blockDim.x + threadIdx.x;
    int n4 = nnz >> 2;
    const int4*   r4 = (const int4*)rows;
    const int4*   c4 = (const int4*)cols;
    const float4* v4 = (const float4*)vals;
    for (int i = tid; i < n4; i += stride) {
        int4 r = __ldg(r4 + i);
        int4 c = __ldg(c4 + i);
        float4 v = __ldg(v4 + i);
        int p0 = atomicAdd(&cur[r.x], 1);
        int p1 = atomicAdd(&cur[r.y], 1);
        int p2 = atomicAdd(&cur[r.z], 1);
        int p3 = atomicAdd(&cur[r.w], 1);
        pack[p0] = make_int2(c.x, __float_as_int(v.x));
        pack[p1] = make_int2(c.y, __float_as_int(v.y));
        pack[p2] = make_int2(c.z, __float_as_int(v.z));
        pack[p3] = make_int2(c.w, __float_as_int(v.w));
    }
    for (int i = n4 * 4 + tid; i < nnz; i += stride) {
        int pos = atomicAdd(&cur[rows[i]], 1);
        pack[pos] = make_int2(cols[i], __float_as_int(vals[i]));
    }
}

// ---------------- CSR SpMM: one warp per output row, float4 per lane ----------------
// out == nullptr -> write to g_S1
template<int S>
__global__ __launch_bounds__(128) void spmm_kernel(const float* __restrict__ dense,
                                                   float* __restrict__ out,
                                                   int nrows) {
    int r = blockIdx.x * 4 + (threadIdx.x >> 5);
    if (r >= nrows) return;
    int lane = threadIdx.x & 31;
    const int*  rowptr = ROWPTR<S>();
    const int2* pack   = PACK<S>();
    int s = __ldg(&rowptr[r]);
    int e = __ldg(&rowptr[r + 1]);
    float* o = out ? out : (float*)g_S1;
    float4 acc = make_float4(0.f, 0.f, 0.f, 0.f);
    int j = s;
    for (; j + 4 <= e; j += 4) {
        int2 p0 = __ldg(&pack[j + 0]);
        int2 p1 = __ldg(&pack[j + 1]);
        int2 p2 = __ldg(&pack[j + 2]);
        int2 p3 = __ldg(&pack[j + 3]);
        float4 d0 = __ldg((const float4*)(dense + (size_t)p0.x * EMB) + lane);
        float4 d1 = __ldg((const float4*)(dense + (size_t)p1.x * EMB) + lane);
        float4 d2 = __ldg((const float4*)(dense + (size_t)p2.x * EMB) + lane);
        float4 d3 = __ldg((const float4*)(dense + (size_t)p3.x * EMB) + lane);
        float v0 = __int_as_float(p0.y), v1 = __int_as_float(p1.y);
        float v2 = __int_as_float(p2.y), v3 = __int_as_float(p3.y);
        acc.x = fmaf(v0, d0.x, acc.x); acc.y = fmaf(v0, d0.y, acc.y);
        acc.z = fmaf(v0, d0.z, acc.z); acc.w = fmaf(v0, d0.w, acc.w);
        acc.x = fmaf(v1, d1.x, acc.x); acc.y = fmaf(v1, d1.y, acc.y);
        acc.z = fmaf(v1, d1.z, acc.z); acc.w = fmaf(v1, d1.w, acc.w);
        acc.x = fmaf(v2, d2.x, acc.x); acc.y = fmaf(v2, d2.y, acc.y);
        acc.z = fmaf(v2, d2.z, acc.z); acc.w = fmaf(v2, d2.w, acc.w);
        acc.x = fmaf(v3, d3.x, acc.x); acc.y = fmaf(v3, d3.y, acc.y);
        acc.z = fmaf(v3, d3.z, acc.z); acc.w = fmaf(v3, d3.w, acc.w);
    }
    for (; j < e; ++j) {
        int2 p = __ldg(&pack[j]);
        float4 d = __ldg((const float4*)(dense + (size_t)p.x * EMB) + lane);
        float v = __int_as_float(p.y);
        acc.x = fmaf(v, d.x, acc.x); acc.y = fmaf(v, d.y, acc.y);
        acc.z = fmaf(v, d.z, acc.z); acc.w = fmaf(v, d.w, acc.w);
    }
    *(float4*)(o + (size_t)r * EMB + lane * 4) = acc;
}

// ---------------- gemmB: F = E @ Wc2 (fp32, hidden off critical path) ----------------
__global__ __launch_bounds__(256) void gemmB_kernel(const float* __restrict__ E,
                                                    float* __restrict__ F,
                                                    int nrows) {
    __shared__ __align__(16) float sA[32][68];
    __shared__ __align__(16) float sB[32][128];
    int tid = threadIdx.x;
    int tr = tid >> 5;
    int tc = tid & 31;
    int row0 = blockIdx.x * 64;
    const float* B = (const float*)g_Wc2;
    float acc[8][4];
#pragma unroll
    for (int i = 0; i < 8; ++i)
#pragma unroll
        for (int c = 0; c < 4; ++c) acc[i][c] = 0.f;

#pragma unroll 1
    for (int chunk = 0; chunk < 4; ++chunk) {
        int k0 = chunk * 32;
#pragma unroll
        for (int q = 0; q < 2; ++q) {
            int lin = tid * 2 + q;
            int m   = lin >> 3;
            int kk  = (lin & 7) << 2;
            float4 a4 = make_float4(0.f, 0.f, 0.f, 0.f);
            if (row0 + m < nrows)
                a4 = *(const float4*)(E + (size_t)(row0 + m) * EMB + k0 + kk);
            sA[kk + 0][m] = a4.x; sA[kk + 1][m] = a4.y;
            sA[kk + 2][m] = a4.z; sA[kk + 3][m] = a4.w;
        }
#pragma unroll
        for (int q = 0; q < 4; ++q) {
            int lin = tid * 4 + q;
            int k = lin >> 5, c4 = lin & 31;
            *(float4*)(&sB[k][c4 * 4]) =
                *(const float4*)(B + (size_t)(k0 + k) * EMB + c4 * 4);
        }
        __syncthreads();
#pragma unroll
        for (int k = 0; k < 32; ++k) {
            float4 b  = *(const float4*)(&sB[k][tc * 4]);
            float4 a0 = *(const float4*)(&sA[k][tr * 8]);
            float4 a1 = *(const float4*)(&sA[k][tr * 8 + 4]);
            float av[8] = {a0.x, a0.y, a0.z, a0.w, a1.x, a1.y, a1.z, a1.w};
#pragma unroll
            for (int i = 0; i < 8; ++i) {
                acc[i][0] = fmaf(av[i], b.x, acc[i][0]);
                acc[i][1] = fmaf(av[i], b.y, acc[i][1]);
                acc[i][2] = fmaf(av[i], b.z, acc[i][2]);
                acc[i][3] = fmaf(av[i], b.w, acc[i][3]);
            }
        }
        __syncthreads();
    }
#pragma unroll
    for (int i = 0; i < 8; ++i) {
        int r = row0 + tr * 8 + i;
        if (r < nrows)
            *(float4*)(F + (size_t)r * EMB + tc * 4) =
                make_float4(acc[i][0], acc[i][1], acc[i][2], acc[i][3]);
    }
}

// ---------------- gemmA (tf32 tensor): F += S1 @ Wc1 ----------------
// block tile 64(M) x 128(N), 8 warps as 4x2 grid of 16x64 warp tiles,
// K=128 staged through smem in 32-chunks as pre-converted tf32 bits.
__device__ __forceinline__ uint32_t f2tf(float x) {
    uint32_t r;
    asm("cvt.rna.tf32.f32 %0, %1;" : "=r"(r) : "f"(x));
    return r;
}

__global__ __launch_bounds__(256) void gemmA_tf32(float* __restrict__ F, int nrows) {
    __shared__ uint32_t sA[64][36];
    __shared__ uint32_t sB[32][132];
    int tid  = threadIdx.x;
    int warp = tid >> 5, lane = tid & 31;
    int g = lane >> 2, t = lane & 3;
    int m0 = (warp & 3) * 16;
    int n0 = (warp >> 2) * 64;
    int row0 = blockIdx.x * 64;
    const float* A = (const float*)g_S1;
    const float* B = (const float*)g_Wc1;

    float acc[8][4];
    int r1 = row0 + m0 + g, r2 = r1 + 8;
#pragma unroll
    for (int ng = 0; ng < 8; ++ng) {
        int c0 = n0 + ng * 8 + t * 2;
        float2 x = (r1 < nrows) ? *(const float2*)(F + (size_t)r1 * EMB + c0)
                                : make_float2(0.f, 0.f);
        float2 y = (r2 < nrows) ? *(const float2*)(F + (size_t)r2 * EMB + c0)
                                : make_float2(0.f, 0.f);
        acc[ng][0] = x.x; acc[ng][1] = x.y; acc[ng][2] = y.x; acc[ng][3] = y.y;
    }

#pragma unroll 1
    for (int chunk = 0; chunk < 4; ++chunk) {
        int k0 = chunk * 32;
#pragma unroll
        for (int q = 0; q < 2; ++q) {
            int lin = tid * 2 + q;
            int m = lin >> 3;
            int kk = (lin & 7) * 4;
            float4 a4 = (row0 + m < nrows)
                ? *(const float4*)(A + (size_t)(row0 + m) * EMB + k0 + kk)
                : make_float4(0.f, 0.f, 0.f, 0.f);
            sA[m][kk + 0] = f2tf(a4.x); sA[m][kk + 1] = f2tf(a4.y);
            sA[m][kk + 2] = f2tf(a4.z); sA[m][kk + 3] = f2tf(a4.w);
        }
#pragma unroll
        for (int q = 0; q < 4; ++q) {
            int lin = tid * 4 + q;
            int k = lin >> 5;
            int c4 = (lin & 31) * 4;
            float4 b4 = *(const float4*)(B + (size_t)(k0 + k) * EMB + c4);
            sB[k][c4 + 0] = f2tf(b4.x); sB[k][c4 + 1] = f2tf(b4.y);
            sB[k][c4 + 2] = f2tf(b4.z); sB[k][c4 + 3] = f2tf(b4.w);
        }
        __syncthreads();
#pragma unroll
        for (int ks = 0; ks < 32; ks += 8) {
            uint32_t a0 = sA[m0 + g][ks + t];
            uint32_t a1 = sA[m0 + g + 8][ks + t];
            uint32_t a2 = sA[m0 + g][ks + t + 4];
            uint32_t a3 = sA[m0 + g + 8][ks + t + 4];
#pragma unroll
            for (int ng = 0; ng < 8; ++ng) {
                uint32_t b0 = sB[ks + t][n0 + ng * 8 + g];
                uint32_t b1 = sB[ks + t + 4][n0 + ng * 8 + g];
                asm volatile(
                    "mma.sync.aligned.m16n8k8.row.col.f32.tf32.tf32.f32 "
                    "{%0,%1,%2,%3}, {%4,%5,%6,%7}, {%8,%9}, {%0,%1,%2,%3};\n"
                    : "+f"(acc[ng][0]), "+f"(acc[ng][1]),
                      "+f"(acc[ng][2]), "+f"(acc[ng][3])
                    : "r"(a0), "r"(a1), "r"(a2), "r"(a3), "r"(b0), "r"(b1));
            }
        }
        __syncthreads();
    }
#pragma unroll
    for (int ng = 0; ng < 8; ++ng) {
        int c0 = n0 + ng * 8 + t * 2;
        if (r1 < nrows)
            *(float2*)(F + (size_t)r1 * EMB + c0) = make_float2(acc[ng][0], acc[ng][1]);
        if (r2 < nrows)
            *(float2*)(F + (size_t)r2 * EMB + c0) = make_float2(acc[ng][2], acc[ng][3]);
    }
}

// ---------------- launch ----------------
template<int S>
static inline void build_csr(const int* rows, const int* cols, const float* vals,
                             int nnz, int nrows, cudaStream_t st) {
    int nblocks = (nrows + SCAN_B - 1) / SCAN_B;
    hist_kernel<S><<<2048, 256, 0, st>>>(rows, nnz);
    scan_pass1<S><<<nblocks, SCAN_B, 0, st>>>(nrows);
    scan_pass3<S><<<nblocks, SCAN_B, 0, st>>>(nrows);
    scatter_kernel<S><<<2048, 256, 0, st>>>(rows, cols, vals, nnz);
}

static cudaStream_t g_s2  = nullptr;   // CSR2 build
static cudaStream_t g_s3  = nullptr;   // wc + gemmB
static cudaEvent_t  g_evF = nullptr;   // fork
static cudaEvent_t  g_evJ = nullptr;   // CSR2 done
static cudaEvent_t  g_evB = nullptr;   // wc+gemmB done

extern "C" void kernel_launch(void* const* d_in, const int* in_sizes, int n_in,
                              void* d_out, int out_size) {
    const float* poi  = (const float*)d_in[0];
    const float* edge = (const float*)d_in[1];
    const int*   pr   = (const int*)d_in[2];
    const int*   pc   = (const int*)d_in[3];
    const float* pv   = (const float*)d_in[4];
    const int*   er   = (const int*)d_in[5];
    const int*   ec   = (const int*)d_in[6];
    const float* evv  = (const float*)d_in[7];
    const float* Wp   = (const float*)d_in[8];
    const float* We   = (const float*)d_in[9];
    const float* Wf   = (const float*)d_in[10];
    int nnz1 = in_sizes[2];
    int nnz2 = in_sizes[5];

    float* prop = (float*)d_out;                       // [100000, 128]
    float* F    = prop + (size_t)N_POI_C * EMB;        // [50000, 128]

    if (!g_s2) {
        cudaStreamCreateWithFlags(&g_s2, cudaStreamNonBlocking);
        cudaStreamCreateWithFlags(&g_s3, cudaStreamNonBlocking);
        cudaEventCreateWithFlags(&g_evF, cudaEventDisableTiming);
        cudaEventCreateWithFlags(&g_evJ, cudaEventDisableTiming);
        cudaEventCreateWithFlags(&g_evB, cudaEventDisableTiming);
    }

    // ---- fork ----
    cudaEventRecord(g_evF, 0);

    // side stream A: CSR build for etp (set 1)
    cudaStreamWaitEvent(g_s2, g_evF, 0);
    build_csr<1>(er, ec, evv, nnz2, N_POI_C, g_s2);
    cudaEventRecord(g_evJ, g_s2);

    // side stream B: weight fold, then F = edge @ Wc2 (both off the critical path)
    cudaStreamWaitEvent(g_s3, g_evF, 0);
    wc_kernel<<<dim3(128, 2), 128, 0, g_s3>>>(Wp, We, Wf);
    gemmB_kernel<<<(N_EDGE_C + 63) / 64, 256, 0, g_s3>>>(edge, F, N_EDGE_C);
    cudaEventRecord(g_evB, g_s3);

    // main (critical path): CSR for pte (set 0), SpMM1 -> S1
    build_csr<0>(pr, pc, pv, nnz1, N_EDGE_C, 0);
    spmm_kernel<0><<<(N_EDGE_C + 3) / 4, 128>>>(poi, nullptr, N_EDGE_C);

    // main: F += S1 @ Wc1 via tf32 tensor cores (needs wc + gemmB done)
    cudaStreamWaitEvent(0, g_evB, 0);
    gemmA_tf32<<<(N_EDGE_C + 63) / 64, 256>>>(F, N_EDGE_C);

    // join CSR2, then SpMM2: prop = etp @ F
    cudaStreamWaitEvent(0, g_evJ, 0);
    spmm_kernel<1><<<(N_POI_C + 3) / 4, 128>>>(F, prop, N_POI_C);
}